// round 1
// baseline (speedup 1.0000x reference)
#include <cuda_runtime.h>
#include <cstdint>

#define NCLS 80
#define CAP  1024
#define NTOT 25200   // (6400+1600+400)*3

// Scratch: per-class candidate lists (key = (~score_bits)<<32 | anchor_idx)
__device__ int d_count[NCLS];
__device__ unsigned long long d_list[NCLS * CAP];

__constant__ float c_anch[9][2] = {
    {10.f,13.f},{16.f,30.f},{33.f,23.f},
    {30.f,61.f},{62.f,45.f},{59.f,119.f},
    {116.f,90.f},{156.f,198.f},{373.f,326.f}
};

__device__ __forceinline__ float sigm(float x) { return 1.0f / (1.0f + expf(-x)); }

__global__ void zero_counts_kernel() {
    if (threadIdx.x < NCLS) d_count[threadIdx.x] = 0;
}

// One thread per (level, anchor, spatial) in anchor-major order within a level
// so that class/reg/obj loads are coalesced across consecutive threads.
__global__ void decode_kernel(const float* __restrict__ ps,
                              const float* __restrict__ pm,
                              const float* __restrict__ pl,
                              float* __restrict__ out) {
    int t = blockIdx.x * blockDim.x + threadIdx.x;
    if (t >= NTOT) return;

    const float* p; int HW, lvl, gbase, tl, ws;
    float stridev;
    if (t < 19200)      { p = ps; HW = 6400; stridev =  8.f; lvl = 0; gbase = 0;     tl = t;         ws = 80; }
    else if (t < 24000) { p = pm; HW = 1600; stridev = 16.f; lvl = 1; gbase = 19200; tl = t - 19200; ws = 40; }
    else                { p = pl; HW =  400; stridev = 32.f; lvl = 2; gbase = 24000; tl = t - 24000; ws = 20; }

    int a = tl / HW;
    int i = tl - a * HW;
    float gx = (float)(i % ws);
    float gy = (float)(i / ws);

    // regression: channels 243 + a*4 + {0,1,2,3}
    const float* pr = p + (size_t)(243 + a * 4) * HW + i;
    float cx = (sigm(pr[0])          + gx) * stridev;
    float cy = (sigm(pr[(size_t)HW]) + gy) * stridev;
    float bw = expf(pr[(size_t)2 * HW]) * c_anch[lvl * 3 + a][0];
    float bh = expf(pr[(size_t)3 * HW]) * c_anch[lvl * 3 + a][1];

    float x1 = fminf(fmaxf((cx - bw * 0.5f) / 640.0f, 0.0f), 1.0f);
    float y1 = fminf(fmaxf((cy - bh * 0.5f) / 640.0f, 0.0f), 1.0f);
    float x2 = fminf(fmaxf((cx + bw * 0.5f) / 640.0f, 0.0f), 1.0f);
    float y2 = fminf(fmaxf((cy + bh * 0.5f) / 640.0f, 0.0f), 1.0f);

    // objectness: channel a
    float obj = sigm(p[(size_t)a * HW + i]);

    // class softmax max + argmax over channels 3 + a*80 + c
    const float* pc = p + (size_t)(3 + a * 80) * HW + i;
    float m = pc[0];
    int am = 0;
    #pragma unroll 8
    for (int c = 1; c < NCLS; c++) {
        float l = pc[(size_t)c * HW];
        if (l > m) { m = l; am = c; }
    }
    float s = 0.0f;
    #pragma unroll 8
    for (int c = 0; c < NCLS; c++)
        s += expf(pc[(size_t)c * HW] - m);

    float score = obj / s;   // softmax_max * obj  (softmax at argmax = 1/s)

    int g = gbase + i * 3 + a;
    float* o = out + (size_t)g * 7;
    o[0] = x1; o[1] = y1; o[2] = x2; o[3] = y2;
    o[4] = score;
    o[5] = (float)am;
    o[6] = 0.0f;

    if (score >= 0.001f) {
        // key: ascending sort => descending score, tie-break ascending idx (stable)
        unsigned long long key =
            (((unsigned long long)(0xFFFFFFFFu - __float_as_uint(score))) << 32) |
            (unsigned long long)(unsigned)g;
        int pos = atomicAdd(&d_count[am], 1);
        if (pos < CAP) d_list[(size_t)am * CAP + pos] = key;
    }
}

// One block per class: bitonic sort candidates by (score desc, idx asc),
// then serial greedy NMS with block-parallel IoU suppression.
__global__ void __launch_bounds__(256, 1) nms_kernel(float* __restrict__ out) {
    int c   = blockIdx.x;
    int tid = threadIdx.x;

    __shared__ unsigned long long keys[CAP];
    __shared__ float bx1[CAP], by1[CAP], bx2[CAP], by2[CAP], ar[CAP];
    __shared__ int   supp[CAP];

    int n = d_count[c];
    if (n > CAP) n = CAP;

    for (int t = tid; t < CAP; t += 256)
        keys[t] = (t < n) ? d_list[(size_t)c * CAP + t] : 0xFFFFFFFFFFFFFFFFULL;
    __syncthreads();

    // bitonic sort ascending over CAP elements
    for (int k = 2; k <= CAP; k <<= 1) {
        for (int j = k >> 1; j > 0; j >>= 1) {
            for (int t = tid; t < CAP; t += 256) {
                int ixj = t ^ j;
                if (ixj > t) {
                    bool up = ((t & k) == 0);
                    unsigned long long a = keys[t], b = keys[ixj];
                    if ((a > b) == up) { keys[t] = b; keys[ixj] = a; }
                }
            }
            __syncthreads();
        }
    }

    // gather boxes in sorted order
    for (int t = tid; t < n; t += 256) {
        int idx = (int)(keys[t] & 0xFFFFFFFFULL);
        const float* o = out + (size_t)idx * 7;
        float a1 = o[0], b1 = o[1], a2 = o[2], b2 = o[3];
        bx1[t] = a1; by1[t] = b1; bx2[t] = a2; by2[t] = b2;
        ar[t]  = (a2 - a1) * (b2 - b1);
        supp[t] = 0;
    }
    __syncthreads();

    // greedy NMS in sorted order
    for (int i = 0; i < n; i++) {
        if (!supp[i]) {
            if (tid == 0)
                out[(size_t)((int)(keys[i] & 0xFFFFFFFFULL)) * 7 + 6] = 1.0f;
            float X1 = bx1[i], Y1 = by1[i], X2 = bx2[i], Y2 = by2[i], A = ar[i];
            for (int j = i + 1 + tid; j < n; j += 256) {
                float xx1 = fmaxf(X1, bx1[j]);
                float yy1 = fmaxf(Y1, by1[j]);
                float xx2 = fminf(X2, bx2[j]);
                float yy2 = fminf(Y2, by2[j]);
                float w = fmaxf(1e-28f, xx2 - xx1);
                float h = fmaxf(1e-28f, yy2 - yy1);
                float inter = w * h;
                float iou = inter / (A + ar[j] - inter);
                if (iou > 0.6f) supp[j] = 1;
            }
        }
        __syncthreads();
    }
}

extern "C" void kernel_launch(void* const* d_in, const int* in_sizes, int n_in,
                              void* d_out, int out_size) {
    const float* ps = (const float*)d_in[0];
    const float* pm = (const float*)d_in[1];
    const float* pl = (const float*)d_in[2];
    float* out = (float*)d_out;

    zero_counts_kernel<<<1, 128>>>();
    decode_kernel<<<(NTOT + 255) / 256, 256>>>(ps, pm, pl, out);
    nms_kernel<<<NCLS, 256>>>(out);
}